// round 1
// baseline (speedup 1.0000x reference)
#include <cuda_runtime.h>
#include <mma.h>
#include <math.h>

using namespace nvcuda;

// Problem constants
#define NE 8
#define NT 8192
#define NH 768
#define NI 3072

// GEMM tiling
#define BM 64
#define BN 64
#define BK 32
#define MAX_TILES 136   // 8192/64 + 8 partial tiles (one per expert) max

// ---------------- device scratch (no allocations allowed) ----------------
__device__ int   g_counts[NE];
__device__ int   g_fill[NE];
__device__ int   g_offsets[NE + 1];
__device__ int   g_perm[NT];            // sorted-position -> token
__device__ int   g_tile_e[MAX_TILES];
__device__ int   g_tile_row0[MAX_TILES];
__device__ int   g_tile_rows[MAX_TILES];
__device__ int   g_ntiles;
__device__ float g_inter[(size_t)NT * NI];  // 96 MB, gelu(x@W1+b1) in sorted order
__device__ float g_mid[(size_t)NT * NH];    // 24 MB, pre-LN (token order)

// ---------------- sort-by-expert kernels ----------------
__global__ void k_zero() {
    int i = threadIdx.x;
    if (i < NE) { g_counts[i] = 0; g_fill[i] = 0; }
}

__global__ void k_count(const int* __restrict__ eid) {
    int t = blockIdx.x * blockDim.x + threadIdx.x;
    if (t < NT) atomicAdd(&g_counts[eid[t]], 1);
}

__global__ void k_build() {
    // single thread: prefix sum + tile table
    int off = 0;
    for (int e = 0; e < NE; e++) { g_offsets[e] = off; off += g_counts[e]; }
    g_offsets[NE] = off;
    int nt = 0;
    for (int e = 0; e < NE; e++) {
        int c = g_counts[e], base = g_offsets[e];
        for (int r = 0; r < c; r += BM) {
            g_tile_e[nt]    = e;
            g_tile_row0[nt] = base + r;
            g_tile_rows[nt] = (c - r < BM) ? (c - r) : BM;
            nt++;
        }
    }
    g_ntiles = nt;
}

__global__ void k_scatter(const int* __restrict__ eid) {
    int t = blockIdx.x * blockDim.x + threadIdx.x;
    if (t < NT) {
        int e = eid[t];
        int pos = g_offsets[e] + atomicAdd(&g_fill[e], 1);
        g_perm[pos] = t;
    }
}

// ---------------- GEMM1: inter = gelu(x[perm] @ W1[e] + b1[e]) ----------------
// grid: (NI/BN, MAX_TILES), block: 128 threads (4 warps, 2x2 warp tiles of 32x32)
__global__ void gemm1(const float* __restrict__ x,
                      const float* __restrict__ w1,
                      const float* __restrict__ b1) {
    int tile = blockIdx.y;
    if (tile >= g_ntiles) return;
    const int e    = g_tile_e[tile];
    const int row0 = g_tile_row0[tile];
    const int rows = g_tile_rows[tile];
    const int n0   = blockIdx.x * BN;

    const float* B = w1 + (size_t)e * NH * NI;   // [H, I] row-major, ld = NI

    __shared__ float As[BM * 36];    // ld 36 (pad)
    __shared__ float Bs[BK * 68];    // ld 68 (pad)
    __shared__ float Cs[BM * 68];    // epilogue staging
    __shared__ int   Ptok[BM];

    const int tid  = threadIdx.x;
    const int warp = tid >> 5;
    const int wm   = warp >> 1;      // 0..1
    const int wn   = warp & 1;       // 0..1

    if (tid < BM) Ptok[tid] = (tid < rows) ? g_perm[row0 + tid] : -1;
    __syncthreads();

    wmma::fragment<wmma::accumulator, 16, 16, 8, float> acc[2][2];
#pragma unroll
    for (int i = 0; i < 2; i++)
#pragma unroll
        for (int j = 0; j < 2; j++) wmma::fill_fragment(acc[i][j], 0.0f);

    for (int k0 = 0; k0 < NH; k0 += BK) {
        // load A tile: 64 rows x 32 cols (gathered by perm)
#pragma unroll
        for (int i = tid; i < BM * (BK / 4); i += 128) {
            int r = i >> 3, c4 = i & 7;
            float4 v = make_float4(0.f, 0.f, 0.f, 0.f);
            int tok = Ptok[r];
            if (tok >= 0)
                v = *(const float4*)(x + (size_t)tok * NH + k0 + c4 * 4);
            *(float4*)(As + r * 36 + c4 * 4) = v;
        }
        // load B tile: 32 rows x 64 cols
#pragma unroll
        for (int i = tid; i < BK * (BN / 4); i += 128) {
            int r = i >> 4, c4 = i & 15;
            float4 v = *(const float4*)(B + (size_t)(k0 + r) * NI + n0 + c4 * 4);
            *(float4*)(Bs + r * 68 + c4 * 4) = v;
        }
        __syncthreads();

#pragma unroll
        for (int kk = 0; kk < BK; kk += 8) {
            wmma::fragment<wmma::matrix_a, 16, 16, 8, wmma::precision::tf32, wmma::row_major> af[2];
            wmma::fragment<wmma::matrix_b, 16, 16, 8, wmma::precision::tf32, wmma::row_major> bf[2];
#pragma unroll
            for (int i = 0; i < 2; i++) {
                wmma::load_matrix_sync(af[i], As + (wm * 32 + i * 16) * 36 + kk, 36);
#pragma unroll
                for (int u = 0; u < af[i].num_elements; u++)
                    af[i].x[u] = wmma::__float_to_tf32(af[i].x[u]);
            }
#pragma unroll
            for (int j = 0; j < 2; j++) {
                wmma::load_matrix_sync(bf[j], Bs + kk * 68 + wn * 32 + j * 16, 68);
#pragma unroll
                for (int u = 0; u < bf[j].num_elements; u++)
                    bf[j].x[u] = wmma::__float_to_tf32(bf[j].x[u]);
            }
#pragma unroll
            for (int i = 0; i < 2; i++)
#pragma unroll
                for (int j = 0; j < 2; j++)
                    wmma::mma_sync(acc[i][j], af[i], bf[j], acc[i][j]);
        }
        __syncthreads();
    }

    // epilogue: stage to SMEM, add bias, exact gelu, store to g_inter (sorted order)
#pragma unroll
    for (int i = 0; i < 2; i++)
#pragma unroll
        for (int j = 0; j < 2; j++)
            wmma::store_matrix_sync(Cs + (wm * 32 + i * 16) * 68 + wn * 32 + j * 16,
                                    acc[i][j], 68, wmma::mem_row_major);
    __syncthreads();

    const float* bias = b1 + (size_t)e * NI + n0;
    for (int i = tid; i < BM * BN; i += 128) {
        int r = i >> 6, c = i & 63;
        if (r < rows) {
            float v = Cs[r * 68 + c] + bias[c];
            float g = 0.5f * v * (1.0f + erff(v * 0.70710678118654752f));
            g_inter[(size_t)(row0 + r) * NI + n0 + c] = g;
        }
    }
}

// ---------------- GEMM2: mid[tok] = inter @ W2[e] + b2[e] + x[tok] ----------------
// grid: (NH/BN, MAX_TILES), block: 128
__global__ void gemm2(const float* __restrict__ x,
                      const float* __restrict__ w2,
                      const float* __restrict__ b2) {
    int tile = blockIdx.y;
    if (tile >= g_ntiles) return;
    const int e    = g_tile_e[tile];
    const int row0 = g_tile_row0[tile];
    const int rows = g_tile_rows[tile];
    const int n0   = blockIdx.x * BN;

    const float* B = w2 + (size_t)e * NI * NH;   // [I, H] row-major, ld = NH

    __shared__ float As[BM * 36];
    __shared__ float Bs[BK * 68];
    __shared__ float Cs[BM * 68];
    __shared__ int   Ptok[BM];

    const int tid  = threadIdx.x;
    const int warp = tid >> 5;
    const int wm   = warp >> 1;
    const int wn   = warp & 1;

    if (tid < BM) Ptok[tid] = (tid < rows) ? g_perm[row0 + tid] : -1;
    __syncthreads();

    wmma::fragment<wmma::accumulator, 16, 16, 8, float> acc[2][2];
#pragma unroll
    for (int i = 0; i < 2; i++)
#pragma unroll
        for (int j = 0; j < 2; j++) wmma::fill_fragment(acc[i][j], 0.0f);

    for (int k0 = 0; k0 < NI; k0 += BK) {
#pragma unroll
        for (int i = tid; i < BM * (BK / 4); i += 128) {
            int r = i >> 3, c4 = i & 7;
            float4 v = make_float4(0.f, 0.f, 0.f, 0.f);
            if (r < rows)
                v = *(const float4*)(g_inter + (size_t)(row0 + r) * NI + k0 + c4 * 4);
            *(float4*)(As + r * 36 + c4 * 4) = v;
        }
#pragma unroll
        for (int i = tid; i < BK * (BN / 4); i += 128) {
            int r = i >> 4, c4 = i & 15;
            float4 v = *(const float4*)(B + (size_t)(k0 + r) * NH + n0 + c4 * 4);
            *(float4*)(Bs + r * 68 + c4 * 4) = v;
        }
        __syncthreads();

#pragma unroll
        for (int kk = 0; kk < BK; kk += 8) {
            wmma::fragment<wmma::matrix_a, 16, 16, 8, wmma::precision::tf32, wmma::row_major> af[2];
            wmma::fragment<wmma::matrix_b, 16, 16, 8, wmma::precision::tf32, wmma::row_major> bf[2];
#pragma unroll
            for (int i = 0; i < 2; i++) {
                wmma::load_matrix_sync(af[i], As + (wm * 32 + i * 16) * 36 + kk, 36);
#pragma unroll
                for (int u = 0; u < af[i].num_elements; u++)
                    af[i].x[u] = wmma::__float_to_tf32(af[i].x[u]);
            }
#pragma unroll
            for (int j = 0; j < 2; j++) {
                wmma::load_matrix_sync(bf[j], Bs + kk * 68 + wn * 32 + j * 16, 68);
#pragma unroll
                for (int u = 0; u < bf[j].num_elements; u++)
                    bf[j].x[u] = wmma::__float_to_tf32(bf[j].x[u]);
            }
#pragma unroll
            for (int i = 0; i < 2; i++)
#pragma unroll
                for (int j = 0; j < 2; j++)
                    wmma::mma_sync(acc[i][j], af[i], bf[j], acc[i][j]);
        }
        __syncthreads();
    }

#pragma unroll
    for (int i = 0; i < 2; i++)
#pragma unroll
        for (int j = 0; j < 2; j++)
            wmma::store_matrix_sync(Cs + (wm * 32 + i * 16) * 68 + wn * 32 + j * 16,
                                    acc[i][j], 68, wmma::mem_row_major);
    __syncthreads();

    const float* bias = b2 + (size_t)e * NH + n0;
    for (int i = tid; i < BM * BN; i += 128) {
        int r = i >> 6, c = i & 63;
        if (r < rows) {
            int tok = Ptok[r];
            float v = Cs[r * 68 + c] + bias[c] + x[(size_t)tok * NH + n0 + c];
            g_mid[(size_t)tok * NH + n0 + c] = v;
        }
    }
}

// ---------------- LayerNorm: out = LN(g_mid) ----------------
__global__ void ln_kernel(const float* __restrict__ gamma,
                          const float* __restrict__ beta,
                          float* __restrict__ out) {
    const int t = blockIdx.x;
    const float* v = g_mid + (size_t)t * NH;
    float* o = out + (size_t)t * NH;

    float s = 0.f, s2 = 0.f;
    for (int h = threadIdx.x; h < NH; h += blockDim.x) {
        float a = v[h];
        s += a; s2 += a * a;
    }
#pragma unroll
    for (int off = 16; off; off >>= 1) {
        s  += __shfl_down_sync(0xffffffffu, s, off);
        s2 += __shfl_down_sync(0xffffffffu, s2, off);
    }
    __shared__ float sh_s[8], sh_s2[8];
    int warp = threadIdx.x >> 5, lane = threadIdx.x & 31;
    if (lane == 0) { sh_s[warp] = s; sh_s2[warp] = s2; }
    __syncthreads();
    float S = 0.f, S2 = 0.f;
#pragma unroll
    for (int i = 0; i < 8; i++) { S += sh_s[i]; S2 += sh_s2[i]; }

    const float inv_h = 1.0f / (float)NH;
    float mean = S * inv_h;
    float var  = S2 * inv_h - mean * mean;
    float rstd = rsqrtf(var + 1e-12f);

    for (int h = threadIdx.x; h < NH; h += blockDim.x)
        o[h] = (v[h] - mean) * rstd * gamma[h] + beta[h];
}

// ---------------- launch ----------------
extern "C" void kernel_launch(void* const* d_in, const int* in_sizes, int n_in,
                              void* d_out, int out_size) {
    const float* x     = (const float*)d_in[0];   // [1,T,H]
    const float* w1    = (const float*)d_in[1];   // [E,H,I]
    const float* b1    = (const float*)d_in[2];   // [E,1,I]
    const float* w2    = (const float*)d_in[3];   // [E,I,H]
    const float* b2    = (const float*)d_in[4];   // [E,1,H]
    const float* gamma = (const float*)d_in[5];   // [H]
    const float* beta  = (const float*)d_in[6];   // [H]
    const int*   eid   = (const int*)d_in[7];     // [T]
    float* out = (float*)d_out;

    k_zero<<<1, 32>>>();
    k_count<<<NT / 256, 256>>>(eid);
    k_build<<<1, 1>>>();
    k_scatter<<<NT / 256, 256>>>(eid);

    gemm1<<<dim3(NI / BN, MAX_TILES), 128>>>(x, w1, b1);
    gemm2<<<dim3(NH / BN, MAX_TILES), 128>>>(x, w2, b2);
    ln_kernel<<<NT, 256>>>(gamma, beta, out);
}

// round 2
// speedup vs baseline: 1.9059x; 1.9059x over previous
#include <cuda_runtime.h>
#include <mma.h>
#include <math.h>

using namespace nvcuda;

#define NE 8
#define NT 8192
#define NH 768
#define NI 3072

#define BM 128
#define BN 128
#define BK 32
#define THREADS 256
#define MAX_TILES 72
#define NTP (NT + NE * BM)   // padded sorted rows: 9216

// smem layout (dynamic): 2 stages of A(128x36) + B(32x132); Cs aliases
#define A_LD 36
#define B_LD 132
#define A_STAGE (BM * A_LD)          // 4608 floats
#define B_STAGE (BK * B_LD)          // 4224 floats
#define SMEM_FLOATS (2 * (A_STAGE + B_STAGE))
#define SMEM_BYTES (SMEM_FLOATS * 4) // 70656; Cs = 128*132*4 = 67584 fits

// ---------------- device scratch ----------------
__device__ int   g_counts[NE];
__device__ int   g_fill[NE];
__device__ int   g_offsets[NE + 1];
__device__ int   g_perm[NTP];
__device__ int   g_tile_e[MAX_TILES];
__device__ int   g_tile_row0[MAX_TILES];
__device__ int   g_ntiles;
__device__ float g_inter[(size_t)NTP * NI];  // 113 MB (sorted+padded)
__device__ float g_mid[(size_t)NT * NH];     // 24 MB (token order)

// ---------------- helpers ----------------
__device__ __forceinline__ void cp_async16(void* dst_smem, const void* src, int src_sz) {
    unsigned dst = (unsigned)__cvta_generic_to_shared(dst_smem);
    asm volatile("cp.async.cg.shared.global [%0], [%1], 16, %2;\n"
                 :: "r"(dst), "l"(src), "r"(src_sz));
}
__device__ __forceinline__ void cp_commit() { asm volatile("cp.async.commit_group;\n"); }
__device__ __forceinline__ void cp_wait1()  { asm volatile("cp.async.wait_group 1;\n"); }
__device__ __forceinline__ void cp_wait0()  { asm volatile("cp.async.wait_group 0;\n"); }

__device__ __forceinline__ float gelu_exact(float v) {
    return 0.5f * v * (1.0f + erff(v * 0.70710678118654752f));
}

// ---------------- sort-by-expert ----------------
__global__ void k_init() {
    int i = blockIdx.x * blockDim.x + threadIdx.x;
    if (i < NTP) g_perm[i] = -1;
    if (i < NE) { g_counts[i] = 0; g_fill[i] = 0; }
}
__global__ void k_count(const int* __restrict__ eid) {
    int t = blockIdx.x * blockDim.x + threadIdx.x;
    if (t < NT) atomicAdd(&g_counts[eid[t]], 1);
}
__global__ void k_build() {
    int off = 0, nt = 0;
    for (int e = 0; e < NE; e++) {
        g_offsets[e] = off;
        int c = g_counts[e];
        for (int r = 0; r < c; r += BM) {
            g_tile_e[nt] = e;
            g_tile_row0[nt] = off + r;
            nt++;
        }
        off += (c + BM - 1) & ~(BM - 1);   // align segments to BM
    }
    g_offsets[NE] = off;
    g_ntiles = nt;
}
__global__ void k_scatter(const int* __restrict__ eid) {
    int t = blockIdx.x * blockDim.x + threadIdx.x;
    if (t < NT) {
        int e = eid[t];
        g_perm[g_offsets[e] + atomicAdd(&g_fill[e], 1)] = t;
    }
}

// ---------------- shared GEMM core macro pieces ----------------
// warp layout: 8 warps as 4(m) x 2(n); warp tile 32 x 64; frags 2x4 of 16x16
struct Frags {
    wmma::fragment<wmma::accumulator, 16, 16, 8, float> acc[2][4];
};

__device__ __forceinline__ void compute_stage(const float* As, const float* Bs,
                                              int wm, int wn, Frags& F) {
#pragma unroll
    for (int kk = 0; kk < BK; kk += 8) {
        wmma::fragment<wmma::matrix_a, 16, 16, 8, wmma::precision::tf32, wmma::row_major> af[2];
        wmma::fragment<wmma::matrix_b, 16, 16, 8, wmma::precision::tf32, wmma::row_major> bf[4];
#pragma unroll
        for (int i = 0; i < 2; i++) {
            wmma::load_matrix_sync(af[i], As + (wm * 32 + i * 16) * A_LD + kk, A_LD);
#pragma unroll
            for (int u = 0; u < af[i].num_elements; u++)
                af[i].x[u] = wmma::__float_to_tf32(af[i].x[u]);
        }
#pragma unroll
        for (int j = 0; j < 4; j++) {
            wmma::load_matrix_sync(bf[j], Bs + kk * B_LD + wn * 64 + j * 16, B_LD);
#pragma unroll
            for (int u = 0; u < bf[j].num_elements; u++)
                bf[j].x[u] = wmma::__float_to_tf32(bf[j].x[u]);
        }
#pragma unroll
        for (int i = 0; i < 2; i++)
#pragma unroll
            for (int j = 0; j < 4; j++)
                wmma::mma_sync(F.acc[i][j], af[i], bf[j], F.acc[i][j]);
    }
}

// ---------------- GEMM1: g_inter = gelu(x[perm] @ W1[e] + b1[e]) ----------------
__global__ void __launch_bounds__(THREADS)
gemm1(const float* __restrict__ x, const float* __restrict__ w1,
      const float* __restrict__ b1) {
    int tile = blockIdx.y;
    if (tile >= g_ntiles) return;
    const int e    = g_tile_e[tile];
    const int row0 = g_tile_row0[tile];
    const int n0   = blockIdx.x * BN;
    const float* W = w1 + (size_t)e * NH * NI;   // ld = NI

    extern __shared__ float smem[];
    float* As = smem;                       // [2][A_STAGE]
    float* Bs = smem + 2 * A_STAGE;         // [2][B_STAGE]
    float* Cs = smem;                       // alias for epilogue
    __shared__ int Ptok[BM];

    const int tid = threadIdx.x;
    const int warp = tid >> 5;
    const int wm = warp >> 1, wn = warp & 1;

    if (tid < BM) Ptok[tid] = g_perm[row0 + tid];
    __syncthreads();

    Frags F;
#pragma unroll
    for (int i = 0; i < 2; i++)
#pragma unroll
        for (int j = 0; j < 4; j++) wmma::fill_fragment(F.acc[i][j], 0.0f);

    const int KT = NH / BK;   // 24

    // stage loader
    auto load_stage = [&](int s, int k0) {
        float* as = As + s * A_STAGE;
        float* bs = Bs + s * B_STAGE;
#pragma unroll
        for (int u = 0; u < 4; u++) {               // A: 1024 float4 / 256 thr
            int i = tid + u * THREADS;
            int r = i >> 3, c4 = (i & 7) * 4;
            int tok = Ptok[r];
            const float* src = (tok >= 0) ? x + (size_t)tok * NH + k0 + c4 : x;
            cp_async16(as + r * A_LD + c4, src, (tok >= 0) ? 16 : 0);
        }
#pragma unroll
        for (int u = 0; u < 4; u++) {               // B: 1024 float4
            int i = tid + u * THREADS;
            int r = i >> 5, c4 = (i & 31) * 4;
            cp_async16(bs + r * B_LD + c4, W + (size_t)(k0 + r) * NI + n0 + c4, 16);
        }
        cp_commit();
    };

    load_stage(0, 0);
    for (int kt = 0; kt < KT; kt++) {
        if (kt + 1 < KT) { load_stage((kt + 1) & 1, (kt + 1) * BK); cp_wait1(); }
        else             { cp_wait0(); }
        __syncthreads();
        int s = kt & 1;
        compute_stage(As + s * A_STAGE, Bs + s * B_STAGE, wm, wn, F);
        __syncthreads();
    }

    // epilogue via smem staging
#pragma unroll
    for (int i = 0; i < 2; i++)
#pragma unroll
        for (int j = 0; j < 4; j++)
            wmma::store_matrix_sync(Cs + (wm * 32 + i * 16) * B_LD + wn * 64 + j * 16,
                                    F.acc[i][j], B_LD, wmma::mem_row_major);
    __syncthreads();

    const float* bias = b1 + (size_t)e * NI + n0;
    for (int i4 = tid; i4 < BM * (BN / 4); i4 += THREADS) {
        int r = i4 >> 5, c4 = (i4 & 31) * 4;
        float4 v = *(const float4*)(Cs + r * B_LD + c4);
        v.x = gelu_exact(v.x + bias[c4 + 0]);
        v.y = gelu_exact(v.y + bias[c4 + 1]);
        v.z = gelu_exact(v.z + bias[c4 + 2]);
        v.w = gelu_exact(v.w + bias[c4 + 3]);
        *(float4*)(g_inter + (size_t)(row0 + r) * NI + n0 + c4) = v;
    }
}

// ---------------- GEMM2: g_mid[tok] = g_inter @ W2[e] + b2[e] + x[tok] ----------------
__global__ void __launch_bounds__(THREADS)
gemm2(const float* __restrict__ x, const float* __restrict__ w2,
      const float* __restrict__ b2) {
    int tile = blockIdx.y;
    if (tile >= g_ntiles) return;
    const int e    = g_tile_e[tile];
    const int row0 = g_tile_row0[tile];
    const int n0   = blockIdx.x * BN;
    const float* W = w2 + (size_t)e * NI * NH;   // ld = NH

    extern __shared__ float smem[];
    float* As = smem;
    float* Bs = smem + 2 * A_STAGE;
    float* Cs = smem;
    __shared__ int Ptok[BM];

    const int tid = threadIdx.x;
    const int warp = tid >> 5;
    const int wm = warp >> 1, wn = warp & 1;

    if (tid < BM) Ptok[tid] = g_perm[row0 + tid];
    __syncthreads();

    Frags F;
#pragma unroll
    for (int i = 0; i < 2; i++)
#pragma unroll
        for (int j = 0; j < 4; j++) wmma::fill_fragment(F.acc[i][j], 0.0f);

    const int KT = NI / BK;   // 96

    auto load_stage = [&](int s, int k0) {
        float* as = As + s * A_STAGE;
        float* bs = Bs + s * B_STAGE;
#pragma unroll
        for (int u = 0; u < 4; u++) {
            int i = tid + u * THREADS;
            int r = i >> 3, c4 = (i & 7) * 4;
            cp_async16(as + r * A_LD + c4,
                       g_inter + (size_t)(row0 + r) * NI + k0 + c4, 16);
        }
#pragma unroll
        for (int u = 0; u < 4; u++) {
            int i = tid + u * THREADS;
            int r = i >> 5, c4 = (i & 31) * 4;
            cp_async16(bs + r * B_LD + c4, W + (size_t)(k0 + r) * NH + n0 + c4, 16);
        }
        cp_commit();
    };

    load_stage(0, 0);
    for (int kt = 0; kt < KT; kt++) {
        if (kt + 1 < KT) { load_stage((kt + 1) & 1, (kt + 1) * BK); cp_wait1(); }
        else             { cp_wait0(); }
        __syncthreads();
        int s = kt & 1;
        compute_stage(As + s * A_STAGE, Bs + s * B_STAGE, wm, wn, F);
        __syncthreads();
    }

#pragma unroll
    for (int i = 0; i < 2; i++)
#pragma unroll
        for (int j = 0; j < 4; j++)
            wmma::store_matrix_sync(Cs + (wm * 32 + i * 16) * B_LD + wn * 64 + j * 16,
                                    F.acc[i][j], B_LD, wmma::mem_row_major);
    __syncthreads();

    const float* bias = b2 + (size_t)e * NH + n0;
    for (int i4 = tid; i4 < BM * (BN / 4); i4 += THREADS) {
        int r = i4 >> 5, c4 = (i4 & 31) * 4;
        int tok = Ptok[r];
        if (tok < 0) continue;
        float4 v = *(const float4*)(Cs + r * B_LD + c4);
        const float4 res = *(const float4*)(x + (size_t)tok * NH + n0 + c4);
        v.x += bias[c4 + 0] + res.x;
        v.y += bias[c4 + 1] + res.y;
        v.z += bias[c4 + 2] + res.z;
        v.w += bias[c4 + 3] + res.w;
        *(float4*)(g_mid + (size_t)tok * NH + n0 + c4) = v;
    }
}

// ---------------- LayerNorm ----------------
__global__ void ln_kernel(const float* __restrict__ gamma,
                          const float* __restrict__ beta,
                          float* __restrict__ out) {
    const int t = blockIdx.x;
    const float* v = g_mid + (size_t)t * NH;
    float* o = out + (size_t)t * NH;

    float s = 0.f, s2 = 0.f;
    for (int h = threadIdx.x; h < NH; h += blockDim.x) {
        float a = v[h];
        s += a; s2 += a * a;
    }
#pragma unroll
    for (int off = 16; off; off >>= 1) {
        s  += __shfl_down_sync(0xffffffffu, s, off);
        s2 += __shfl_down_sync(0xffffffffu, s2, off);
    }
    __shared__ float sh_s[8], sh_s2[8];
    int warp = threadIdx.x >> 5, lane = threadIdx.x & 31;
    if (lane == 0) { sh_s[warp] = s; sh_s2[warp] = s2; }
    __syncthreads();
    float S = 0.f, S2 = 0.f;
#pragma unroll
    for (int i = 0; i < 8; i++) { S += sh_s[i]; S2 += sh_s2[i]; }

    const float inv_h = 1.0f / (float)NH;
    float mean = S * inv_h;
    float var  = S2 * inv_h - mean * mean;
    float rstd = rsqrtf(var + 1e-12f);

    for (int h = threadIdx.x; h < NH; h += blockDim.x)
        o[h] = (v[h] - mean) * rstd * gamma[h] + beta[h];
}

// ---------------- launch ----------------
extern "C" void kernel_launch(void* const* d_in, const int* in_sizes, int n_in,
                              void* d_out, int out_size) {
    const float* x     = (const float*)d_in[0];
    const float* w1    = (const float*)d_in[1];
    const float* b1    = (const float*)d_in[2];
    const float* w2    = (const float*)d_in[3];
    const float* b2    = (const float*)d_in[4];
    const float* gamma = (const float*)d_in[5];
    const float* beta  = (const float*)d_in[6];
    const int*   eid   = (const int*)d_in[7];
    float* out = (float*)d_out;

    static bool attr_set = false;
    if (!attr_set) {
        cudaFuncSetAttribute(gemm1, cudaFuncAttributeMaxDynamicSharedMemorySize, SMEM_BYTES);
        cudaFuncSetAttribute(gemm2, cudaFuncAttributeMaxDynamicSharedMemorySize, SMEM_BYTES);
        attr_set = true;
    }

    k_init<<<(NTP + 255) / 256, 256>>>();
    k_count<<<NT / 256, 256>>>(eid);
    k_build<<<1, 1>>>();
    k_scatter<<<NT / 256, 256>>>(eid);

    gemm1<<<dim3(NI / BN, MAX_TILES), THREADS, SMEM_BYTES>>>(x, w1, b1);
    gemm2<<<dim3(NH / BN, MAX_TILES), THREADS, SMEM_BYTES>>>(x, w2, b2);
    ln_kernel<<<NT, 256>>>(gamma, beta, out);
}